// round 2
// baseline (speedup 1.0000x reference)
#include <cuda_runtime.h>
#include <float.h>
#include <stdint.h>

#define NODES 65536
#define HD 128
#define THREADS 256
#define TSTRIDE 132
#define EDGE_SMEM ((128 * TSTRIDE + 16 * 128) * 4 + 128 * 4)

// Scratch (allowed: __device__ globals, no runtime allocation)
__device__ float g_A[(size_t)NODES * HD];
__device__ float g_B[(size_t)NODES * HD];
__device__ float g_agg[(size_t)NODES * HD];
__device__ float g_h0[(size_t)NODES * HD];
__device__ float g_tmp[(size_t)NODES * HD];

__global__ __launch_bounds__(THREADS) void fill_kernel(float4* p, float v, int n4) {
    int i = blockIdx.x * blockDim.x + threadIdx.x;
    if (i < n4) p[i] = make_float4(v, v, v, v);
}

// Out[M,128] = act( In[M,128] @ W[128,128] (+bias) (+addend) ), tile 128x128/block
__global__ __launch_bounds__(THREADS) void gemm_kernel(
    const float* __restrict__ In, const float* __restrict__ W,
    const float* __restrict__ bias, const float* __restrict__ addend,
    float* __restrict__ Out, int relu_out)
{
    __shared__ float sIn[16 * 128];  // [k][row] (transposed chunk)
    __shared__ float sW[16 * 128];   // [k][col]

    int tid = threadIdx.x;
    int rowBase = blockIdx.x * 128;
    int tx = tid & 15, ty = tid >> 4;  // cols tx*8..+7, rows ty*8..+7

    float acc[8][8];
#pragma unroll
    for (int i = 0; i < 8; i++)
#pragma unroll
        for (int j = 0; j < 8; j++) acc[i][j] = 0.f;

    for (int kk = 0; kk < HD; kk += 16) {
#pragma unroll
        for (int l = 0; l < 2; l++) {
            int idx = tid + l * THREADS;          // 0..511
            int r = idx >> 2, c4 = idx & 3;       // row, which float4 of chunk
            float4 v = *(const float4*)(In + (size_t)(rowBase + r) * HD + kk + c4 * 4);
            sIn[(c4 * 4 + 0) * 128 + r] = v.x;
            sIn[(c4 * 4 + 1) * 128 + r] = v.y;
            sIn[(c4 * 4 + 2) * 128 + r] = v.z;
            sIn[(c4 * 4 + 3) * 128 + r] = v.w;
        }
#pragma unroll
        for (int l = 0; l < 2; l++) {
            int idx = tid + l * THREADS;
            int k = idx >> 5, c = idx & 31;
            *(float4*)(sW + k * 128 + c * 4) =
                *(const float4*)(W + (size_t)(kk + k) * HD + c * 4);
        }
        __syncthreads();
#pragma unroll
        for (int k = 0; k < 16; k++) {
            float a[8], b[8];
            *(float4*)(a)     = *(const float4*)(sIn + k * 128 + ty * 8);
            *(float4*)(a + 4) = *(const float4*)(sIn + k * 128 + ty * 8 + 4);
            *(float4*)(b)     = *(const float4*)(sW + k * 128 + tx * 8);
            *(float4*)(b + 4) = *(const float4*)(sW + k * 128 + tx * 8 + 4);
#pragma unroll
            for (int i = 0; i < 8; i++)
#pragma unroll
                for (int j = 0; j < 8; j++) acc[i][j] += a[i] * b[j];
        }
        __syncthreads();
    }

    float bv[8];
    if (bias) {
        *(float4*)(bv)     = *(const float4*)(bias + tx * 8);
        *(float4*)(bv + 4) = *(const float4*)(bias + tx * 8 + 4);
    } else {
#pragma unroll
        for (int j = 0; j < 8; j++) bv[j] = 0.f;
    }
#pragma unroll
    for (int i = 0; i < 8; i++) {
        size_t row = (size_t)rowBase + ty * 8 + i;
        float o[8];
#pragma unroll
        for (int j = 0; j < 8; j++) o[j] = acc[i][j] + bv[j];
        if (addend) {
            float4 a0 = *(const float4*)(addend + row * HD + tx * 8);
            float4 a1 = *(const float4*)(addend + row * HD + tx * 8 + 4);
            o[0] += a0.x; o[1] += a0.y; o[2] += a0.z; o[3] += a0.w;
            o[4] += a1.x; o[5] += a1.y; o[6] += a1.z; o[7] += a1.w;
        }
        if (relu_out) {
#pragma unroll
            for (int j = 0; j < 8; j++) o[j] = fmaxf(o[j], 0.f);
        }
        *(float4*)(Out + row * HD + tx * 8)     = make_float4(o[0], o[1], o[2], o[3]);
        *(float4*)(Out + row * HD + tx * 8 + 4) = make_float4(o[4], o[5], o[6], o[7]);
    }
}

// Per edge e (incl. self loops): t = relu(A[src]-B[dst]); h = t@W2 + b2;
// agg[dst] = max(agg[dst], h) elementwise.  128 edges per CTA, tile GEMM.
__global__ __launch_bounds__(THREADS) void edge_kernel(
    const int* __restrict__ ei,  // [2,E] int32
    const float* __restrict__ A, const float* __restrict__ B,
    const float* __restrict__ W2, const float* __restrict__ b2,
    float* __restrict__ agg, int E, int total)
{
    extern __shared__ float smem[];
    float* sT = smem;                    // [128][TSTRIDE]
    float* sW = smem + 128 * TSTRIDE;    // [16][128]
    int* sDst = (int*)(sW + 16 * 128);   // [128]

    int tid = threadIdx.x;
    int eBase = blockIdx.x * 128;

    // Gather + subtract + relu into sT (2 threads per edge, float4 coalesced)
    {
        int le = tid >> 1, half = tid & 1;
        int e = eBase + le;
        int s = 0, d = 0;
        bool valid = (e < total);
        if (e < E) {
            s = ei[e];
            d = ei[(size_t)E + e];
        } else if (valid) {
            s = e - E;  // self loop
            d = s;
        }
        if (half == 0) sDst[le] = d;
        const float4* Ar = (const float4*)(A + (size_t)s * HD) + half * 16;
        const float4* Br = (const float4*)(B + (size_t)d * HD) + half * 16;
        float* Tr = sT + le * TSTRIDE + half * 64;
#pragma unroll
        for (int q = 0; q < 16; q++) {
            float4 av = Ar[q], bw = Br[q];
            float4 t;
            t.x = valid ? fmaxf(av.x - bw.x, 0.f) : 0.f;
            t.y = valid ? fmaxf(av.y - bw.y, 0.f) : 0.f;
            t.z = valid ? fmaxf(av.z - bw.z, 0.f) : 0.f;
            t.w = valid ? fmaxf(av.w - bw.w, 0.f) : 0.f;
            *(float4*)(Tr + q * 4) = t;
        }
    }

    int tx = tid & 15, ty = tid >> 4;
    float acc[8][8];
#pragma unroll
    for (int i = 0; i < 8; i++)
#pragma unroll
        for (int j = 0; j < 8; j++) acc[i][j] = 0.f;

    for (int kk = 0; kk < HD; kk += 16) {
#pragma unroll
        for (int l = 0; l < 2; l++) {
            int idx = tid + l * THREADS;
            int k = idx >> 5, c = idx & 31;
            *(float4*)(sW + k * 128 + c * 4) =
                *(const float4*)(W2 + (size_t)(kk + k) * HD + c * 4);
        }
        __syncthreads();
#pragma unroll
        for (int k = 0; k < 16; k++) {
            float b[8];
            *(float4*)(b)     = *(const float4*)(sW + k * 128 + tx * 8);
            *(float4*)(b + 4) = *(const float4*)(sW + k * 128 + tx * 8 + 4);
            float a[8];
#pragma unroll
            for (int i = 0; i < 8; i++) a[i] = sT[(ty * 8 + i) * TSTRIDE + kk + k];
#pragma unroll
            for (int i = 0; i < 8; i++)
#pragma unroll
                for (int j = 0; j < 8; j++) acc[i][j] += a[i] * b[j];
        }
        __syncthreads();
    }

    float bv[8];
    *(float4*)(bv)     = *(const float4*)(b2 + tx * 8);
    *(float4*)(bv + 4) = *(const float4*)(b2 + tx * 8 + 4);

#pragma unroll
    for (int i = 0; i < 8; i++) {
        int le = ty * 8 + i;
        int e = eBase + le;
        if (e >= total) continue;
        int d = sDst[le];
        float* base = agg + (size_t)d * HD + tx * 8;
#pragma unroll
        for (int j = 0; j < 8; j++) {
            float v = acc[i][j] + bv[j];
            if (v >= 0.f)
                atomicMax((int*)(base + j), __float_as_int(v));
            else
                atomicMin((unsigned int*)(base + j), __float_as_uint(v));
        }
    }
}

extern "C" void kernel_launch(void* const* d_in, const int* in_sizes, int n_in,
                              void* d_out, int out_size)
{
    (void)n_in; (void)out_size;
    const float* x   = (const float*)d_in[0];
    const float* pos = (const float*)d_in[1];
    const int* ei    = (const int*)d_in[2];
    const float* p[16];
    for (int i = 0; i < 16; i++) p[i] = (const float*)d_in[3 + i];
    // p layout per layer (8 each): lw1, lb1, lw2, lb2, gw1, gb1, gw2, gb2

    int E = in_sizes[2] / 2;
    int total = E + NODES;

    float *A, *B, *AGG, *H0, *TMP;
    cudaGetSymbolAddress((void**)&A, g_A);
    cudaGetSymbolAddress((void**)&B, g_B);
    cudaGetSymbolAddress((void**)&AGG, g_agg);
    cudaGetSymbolAddress((void**)&H0, g_h0);
    cudaGetSymbolAddress((void**)&TMP, g_tmp);

    cudaFuncSetAttribute(edge_kernel, cudaFuncAttributeMaxDynamicSharedMemorySize, EDGE_SMEM);

    int gemmBlocks = NODES / 128;                 // 512
    int edgeBlocks = (total + 127) / 128;         // 8704
    int fillBlocks = (NODES * HD / 4 + THREADS - 1) / THREADS;

    for (int layer = 0; layer < 2; layer++) {
        const float* lw1 = p[layer * 8 + 0];
        const float* lb1 = p[layer * 8 + 1];
        const float* lw2 = p[layer * 8 + 2];
        const float* lb2 = p[layer * 8 + 3];
        const float* gw1 = p[layer * 8 + 4];
        const float* gb1 = p[layer * 8 + 5];
        const float* gw2 = p[layer * 8 + 6];
        const float* gb2 = p[layer * 8 + 7];
        const float* inx = (layer == 0) ? x : H0;
        float* outp = (layer == 0) ? H0 : (float*)d_out;

        // B = pos @ Wp          (Wp = lw1 rows 128..255)
        gemm_kernel<<<gemmBlocks, THREADS>>>(pos, lw1 + 128 * HD, nullptr, nullptr, B, 0);
        // A = inx @ Wx + B + lb1 (Wx = lw1 rows 0..127)
        gemm_kernel<<<gemmBlocks, THREADS>>>(inx, lw1, lb1, B, A, 0);
        // agg = -FLT_MAX
        fill_kernel<<<fillBlocks, THREADS>>>((float4*)AGG, -FLT_MAX, NODES * HD / 4);
        // per-edge local_nn layer2 + segment max
        edge_kernel<<<edgeBlocks, THREADS, EDGE_SMEM>>>(ei, A, B, lw2, lb2, AGG, E, total);
        // global_nn
        gemm_kernel<<<gemmBlocks, THREADS>>>(AGG, gw1, gb1, nullptr, TMP, 1);
        gemm_kernel<<<gemmBlocks, THREADS>>>(TMP, gw2, gb2, nullptr, outp, 0);
    }
}

// round 4
// speedup vs baseline: 1.5097x; 1.5097x over previous
#include <cuda_runtime.h>
#include <float.h>
#include <stdint.h>

#define NODES 65536
#define HD 128
#define THREADS 256
#define TS 132                       // smem row stride (floats) for sT/sW

// smem: [0:512) sDst | [512:1024) sBias | [1024:+67584) sT | then sW
#define SM_T 1024
#define SM_W (1024 + 128 * TS * 4)
#define EDGE_SMEM (1024 + 2 * 128 * TS * 4)

// ---------------- scratch ----------------
__device__ float g_A[(size_t)NODES * HD];
__device__ float g_B[(size_t)NODES * HD];
__device__ float g_agg[(size_t)NODES * HD];
__device__ float g_h0[(size_t)NODES * HD];
__device__ float g_tmp[(size_t)NODES * HD];
__device__ float g_w2t[HD * HD];     // W2^T, tf32-rounded, [n][k]

__global__ __launch_bounds__(THREADS) void fill_kernel(float4* p, float v, int n4) {
    int i = blockIdx.x * blockDim.x + threadIdx.x;
    if (i < n4) p[i] = make_float4(v, v, v, v);
}

// W2[k][n] -> W2T[n][k], tf32-rounded
__global__ __launch_bounds__(HD) void prep_w2t_kernel(
    const float* __restrict__ W2, float* __restrict__ out)
{
    int n = blockIdx.x, k = threadIdx.x;
    float v = W2[k * HD + n];
    asm("cvt.rna.tf32.f32 %0, %0;" : "+f"(v));
    out[n * HD + k] = v;
}

// ---------------- node GEMM (fp32 FFMA, proven in R2) ----------------
__global__ __launch_bounds__(THREADS) void gemm_kernel(
    const float* __restrict__ In, const float* __restrict__ W,
    const float* __restrict__ bias, const float* __restrict__ addend,
    float* __restrict__ Out, int relu_out)
{
    __shared__ float sIn[16 * 128];
    __shared__ float sW[16 * 128];

    int tid = threadIdx.x;
    int rowBase = blockIdx.x * 128;
    int tx = tid & 15, ty = tid >> 4;

    float acc[8][8];
#pragma unroll
    for (int i = 0; i < 8; i++)
#pragma unroll
        for (int j = 0; j < 8; j++) acc[i][j] = 0.f;

    for (int kk = 0; kk < HD; kk += 16) {
#pragma unroll
        for (int l = 0; l < 2; l++) {
            int idx = tid + l * THREADS;
            int r = idx >> 2, c4 = idx & 3;
            float4 v = *(const float4*)(In + (size_t)(rowBase + r) * HD + kk + c4 * 4);
            sIn[(c4 * 4 + 0) * 128 + r] = v.x;
            sIn[(c4 * 4 + 1) * 128 + r] = v.y;
            sIn[(c4 * 4 + 2) * 128 + r] = v.z;
            sIn[(c4 * 4 + 3) * 128 + r] = v.w;
        }
#pragma unroll
        for (int l = 0; l < 2; l++) {
            int idx = tid + l * THREADS;
            int k = idx >> 5, c = idx & 31;
            *(float4*)(sW + k * 128 + c * 4) =
                *(const float4*)(W + (size_t)(kk + k) * HD + c * 4);
        }
        __syncthreads();
#pragma unroll
        for (int k = 0; k < 16; k++) {
            float a[8], b[8];
            *(float4*)(a)     = *(const float4*)(sIn + k * 128 + ty * 8);
            *(float4*)(a + 4) = *(const float4*)(sIn + k * 128 + ty * 8 + 4);
            *(float4*)(b)     = *(const float4*)(sW + k * 128 + tx * 8);
            *(float4*)(b + 4) = *(const float4*)(sW + k * 128 + tx * 8 + 4);
#pragma unroll
            for (int i = 0; i < 8; i++)
#pragma unroll
                for (int j = 0; j < 8; j++) acc[i][j] += a[i] * b[j];
        }
        __syncthreads();
    }

    float bv[8];
    if (bias) {
        *(float4*)(bv)     = *(const float4*)(bias + tx * 8);
        *(float4*)(bv + 4) = *(const float4*)(bias + tx * 8 + 4);
    } else {
#pragma unroll
        for (int j = 0; j < 8; j++) bv[j] = 0.f;
    }
#pragma unroll
    for (int i = 0; i < 8; i++) {
        size_t row = (size_t)rowBase + ty * 8 + i;
        float o[8];
#pragma unroll
        for (int j = 0; j < 8; j++) o[j] = acc[i][j] + bv[j];
        if (addend) {
            float4 a0 = *(const float4*)(addend + row * HD + tx * 8);
            float4 a1 = *(const float4*)(addend + row * HD + tx * 8 + 4);
            o[0] += a0.x; o[1] += a0.y; o[2] += a0.z; o[3] += a0.w;
            o[4] += a1.x; o[5] += a1.y; o[6] += a1.z; o[7] += a1.w;
        }
        if (relu_out) {
#pragma unroll
            for (int j = 0; j < 8; j++) o[j] = fmaxf(o[j], 0.f);
        }
        *(float4*)(Out + row * HD + tx * 8)     = make_float4(o[0], o[1], o[2], o[3]);
        *(float4*)(Out + row * HD + tx * 8 + 4) = make_float4(o[4], o[5], o[6], o[7]);
    }
}

// ---------------- edge kernel: tf32 mma.sync tile GEMM + atomic max ----------------
__device__ __forceinline__ void mma_tf32(float* d, const uint32_t* a, const uint32_t* b) {
    asm volatile(
        "mma.sync.aligned.m16n8k8.row.col.f32.tf32.tf32.f32 "
        "{%0,%1,%2,%3}, {%4,%5,%6,%7}, {%8,%9}, {%0,%1,%2,%3};"
        : "+f"(d[0]), "+f"(d[1]), "+f"(d[2]), "+f"(d[3])
        : "r"(a[0]), "r"(a[1]), "r"(a[2]), "r"(a[3]), "r"(b[0]), "r"(b[1]));
}

__global__ __launch_bounds__(THREADS) void edge_mma_kernel(
    const int* __restrict__ ei,
    const float* __restrict__ A, const float* __restrict__ B,
    const float* __restrict__ W2T, const float* __restrict__ b2,
    float* __restrict__ agg, int E, int total)
{
    extern __shared__ char smem[];
    int* sDst = (int*)smem;
    float* sBias = (float*)(smem + 512);
    float* sT = (float*)(smem + SM_T);
    float* sW = (float*)(smem + SM_W);

    int tid = threadIdx.x;
    int lane = tid & 31, wid = tid >> 5;
    int eBase = blockIdx.x * 128;

    // Stream W2T into sW (padded rows) via cp.async, overlapping the gather
    {
        uint32_t sw_base;
        asm("{ .reg .u64 t; cvta.to.shared.u64 t, %1; cvt.u32.u64 %0, t; }"
            : "=r"(sw_base) : "l"(sW));
#pragma unroll
        for (int it = 0; it < 16; it++) {
            int linear = tid + it * THREADS;       // float4 index 0..4095
            int n = linear >> 5, c4 = linear & 31;
            uint32_t dst = sw_base + (uint32_t)(n * TS + c4 * 4) * 4;
            asm volatile("cp.async.cg.shared.global [%0], [%1], 16;"
                         :: "r"(dst), "l"(W2T + (size_t)linear * 4));
        }
        asm volatile("cp.async.commit_group;" ::: "memory");
    }

    if (tid < 128) sBias[tid] = b2[tid];

    // Gather: t = relu(A[src]-B[dst]) -> tf32 -> sT[row][k] (2 threads per row)
    {
        int r = tid >> 1, half = tid & 1;
        int e = eBase + r;
        int s, d;
        bool valid = e < total;
        if (e < E) { s = ei[e]; d = ei[E + e]; }
        else if (valid) { s = e - E; d = s; }
        else { s = 0; d = 0; }
        if (half == 0) sDst[r] = d;
        const float4* Ar = (const float4*)(A + (size_t)s * HD) + half * 16;
        const float4* Br = (const float4*)(B + (size_t)d * HD) + half * 16;
        float* Tr = sT + r * TS + half * 64;
#pragma unroll
        for (int q = 0; q < 16; q++) {
            float4 av = Ar[q], bw = Br[q];
            float4 t;
            t.x = valid ? fmaxf(av.x - bw.x, 0.f) : 0.f;
            t.y = valid ? fmaxf(av.y - bw.y, 0.f) : 0.f;
            t.z = valid ? fmaxf(av.z - bw.z, 0.f) : 0.f;
            t.w = valid ? fmaxf(av.w - bw.w, 0.f) : 0.f;
            asm("cvt.rna.tf32.f32 %0, %0;" : "+f"(t.x));
            asm("cvt.rna.tf32.f32 %0, %0;" : "+f"(t.y));
            asm("cvt.rna.tf32.f32 %0, %0;" : "+f"(t.z));
            asm("cvt.rna.tf32.f32 %0, %0;" : "+f"(t.w));
            *(float4*)(Tr + q * 4) = t;
        }
    }

    asm volatile("cp.async.wait_group 0;" ::: "memory");
    __syncthreads();

    // Warp tiles: warpM = wid&1 (rows 64), warpN = wid>>1 (cols 32)
    int rowBase = (wid & 1) * 64;
    int colBase = (wid >> 1) * 32;
    int g = lane >> 2, tg = lane & 3;

    float acc[4][4][4];
#pragma unroll
    for (int i = 0; i < 4; i++)
#pragma unroll
        for (int j = 0; j < 4; j++)
#pragma unroll
            for (int q = 0; q < 4; q++) acc[i][j][q] = 0.f;

    const uint32_t* sTu = (const uint32_t*)sT;
    const uint32_t* sWu = (const uint32_t*)sW;

#pragma unroll
    for (int ks = 0; ks < 16; ks++) {
        int kk = ks * 8;
        uint32_t b[4][2];
#pragma unroll
        for (int nf = 0; nf < 4; nf++) {
            int n = colBase + nf * 8 + g;
            b[nf][0] = sWu[n * TS + kk + tg];
            b[nf][1] = sWu[n * TS + kk + tg + 4];
        }
        uint32_t a[4][4];
#pragma unroll
        for (int mf = 0; mf < 4; mf++) {
            int r = rowBase + mf * 16 + g;
            a[mf][0] = sTu[r * TS + kk + tg];
            a[mf][1] = sTu[(r + 8) * TS + kk + tg];
            a[mf][2] = sTu[r * TS + kk + tg + 4];
            a[mf][3] = sTu[(r + 8) * TS + kk + tg + 4];
        }
#pragma unroll
        for (int mf = 0; mf < 4; mf++)
#pragma unroll
            for (int nf = 0; nf < 4; nf++)
                mma_tf32(acc[mf][nf], a[mf], b[nf]);
    }

    // Epilogue: bias + float atomic max into agg[dst]
#pragma unroll
    for (int mf = 0; mf < 4; mf++) {
        int r0 = rowBase + mf * 16 + g;
        int r1 = r0 + 8;
        int e0 = eBase + r0, e1 = eBase + r1;
        bool v0 = e0 < total, v1 = e1 < total;
        float* base0 = agg + (size_t)sDst[r0] * HD;
        float* base1 = agg + (size_t)sDst[r1] * HD;
#pragma unroll
        for (int nf = 0; nf < 4; nf++) {
            int c0 = colBase + nf * 8 + 2 * tg;
            float bias0 = sBias[c0], bias1 = sBias[c0 + 1];
#pragma unroll
            for (int q = 0; q < 4; q++) {
                bool rowsel = (q >= 2);
                bool valid = rowsel ? v1 : v0;
                if (!valid) continue;
                float* base = rowsel ? base1 : base0;
                int col = c0 + (q & 1);
                float v = acc[mf][nf][q] + ((q & 1) ? bias1 : bias0);
                float* p = base + col;
                if (v >= 0.f) atomicMax((int*)p, __float_as_int(v));
                else          atomicMin((unsigned int*)p, __float_as_uint(v));
            }
        }
    }
}

// ---------------- launch ----------------
extern "C" void kernel_launch(void* const* d_in, const int* in_sizes, int n_in,
                              void* d_out, int out_size)
{
    (void)n_in; (void)out_size;
    const float* x   = (const float*)d_in[0];
    const float* pos = (const float*)d_in[1];
    const int* ei    = (const int*)d_in[2];
    const float* p[16];
    for (int i = 0; i < 16; i++) p[i] = (const float*)d_in[3 + i];

    int E = in_sizes[2] / 2;
    int total = E + NODES;

    float *A, *B, *AGG, *H0, *TMP, *W2T;
    cudaGetSymbolAddress((void**)&A, g_A);
    cudaGetSymbolAddress((void**)&B, g_B);
    cudaGetSymbolAddress((void**)&AGG, g_agg);
    cudaGetSymbolAddress((void**)&H0, g_h0);
    cudaGetSymbolAddress((void**)&TMP, g_tmp);
    cudaGetSymbolAddress((void**)&W2T, g_w2t);

    cudaFuncSetAttribute(edge_mma_kernel, cudaFuncAttributeMaxDynamicSharedMemorySize, EDGE_SMEM);

    int gemmBlocks = NODES / 128;              // 512
    int edgeBlocks = (total + 127) / 128;      // 8704
    int fillBlocks = (NODES * HD / 4 + THREADS - 1) / THREADS;

    for (int layer = 0; layer < 2; layer++) {
        const float* lw1 = p[layer * 8 + 0];
        const float* lb1 = p[layer * 8 + 1];
        const float* lw2 = p[layer * 8 + 2];
        const float* lb2 = p[layer * 8 + 3];
        const float* gw1 = p[layer * 8 + 4];
        const float* gb1 = p[layer * 8 + 5];
        const float* gw2 = p[layer * 8 + 6];
        const float* gb2 = p[layer * 8 + 7];
        const float* inx = (layer == 0) ? x : H0;
        float* outp = (layer == 0) ? H0 : (float*)d_out;

        gemm_kernel<<<gemmBlocks, THREADS>>>(pos, lw1 + 128 * HD, nullptr, nullptr, B, 0);
        gemm_kernel<<<gemmBlocks, THREADS>>>(inx, lw1, lb1, B, A, 0);
        prep_w2t_kernel<<<HD, HD>>>(lw2, W2T);
        fill_kernel<<<fillBlocks, THREADS>>>((float4*)AGG, -FLT_MAX, NODES * HD / 4);
        edge_mma_kernel<<<edgeBlocks, THREADS, EDGE_SMEM>>>(ei, A, B, W2T, lb2, AGG, E, total);
        gemm_kernel<<<gemmBlocks, THREADS>>>(AGG, gw1, gb1, nullptr, TMP, 1);
        gemm_kernel<<<gemmBlocks, THREADS>>>(TMP, gw2, gb2, nullptr, outp, 0);
    }
}

// round 5
// speedup vs baseline: 1.6218x; 1.0742x over previous
#include <cuda_runtime.h>
#include <float.h>
#include <stdint.h>

#define NODES 65536
#define HD 128
#define THREADS 256
#define TS 132                       // smem row stride (floats) for sT/sW
#define MAXEDGES (1048576 + NODES)

// smem: [0:512) sDst | [512:1024) sBias | [1024:+67584) sT | then sW
#define SM_T 1024
#define SM_W (1024 + 128 * TS * 4)
#define EDGE_SMEM (1024 + 2 * 128 * TS * 4)

// ---------------- scratch ----------------
__device__ float g_A[(size_t)NODES * HD];
__device__ float g_B[(size_t)NODES * HD];
__device__ float g_agg[(size_t)NODES * HD];
__device__ float g_h0[(size_t)NODES * HD];
__device__ float g_tmp[(size_t)NODES * HD];
__device__ float g_w2t[HD * HD];     // W2^T, tf32-rounded, [n][k]
__device__ int g_cnt[NODES];
__device__ int g_next[NODES];
__device__ int g_ssrc[MAXEDGES];
__device__ int g_sdst[MAXEDGES];

__global__ __launch_bounds__(THREADS) void fill_kernel(float4* p, float v, int n4) {
    int i = blockIdx.x * blockDim.x + threadIdx.x;
    if (i < n4) p[i] = make_float4(v, v, v, v);
}

__global__ __launch_bounds__(THREADS) void zero_i32(int* p, int n) {
    int i = blockIdx.x * blockDim.x + threadIdx.x;
    if (i < n) p[i] = 0;
}

// ---------------- counting sort by dst (once per launch) ----------------
__global__ __launch_bounds__(THREADS) void hist_kernel(
    const int* __restrict__ ei, int* __restrict__ cnt, int E, int total)
{
    int e = blockIdx.x * blockDim.x + threadIdx.x;
    if (e < total) {
        int d = (e < E) ? ei[E + e] : (e - E);
        atomicAdd(&cnt[d], 1);
    }
}

#define SCAN_T 1024
#define CHUNK (NODES / SCAN_T)   // 64
__global__ __launch_bounds__(SCAN_T) void scan_kernel(
    const int* __restrict__ cnt, int* __restrict__ next)
{
    __shared__ int part[SCAN_T];
    int t = threadIdx.x;
    int base = t * CHUNK;
    int sum = 0;
#pragma unroll 4
    for (int i = 0; i < CHUNK; i++) sum += cnt[base + i];
    part[t] = sum;
    __syncthreads();
    // Hillis-Steele inclusive scan
    for (int off = 1; off < SCAN_T; off <<= 1) {
        int v = (t >= off) ? part[t - off] : 0;
        __syncthreads();
        part[t] += v;
        __syncthreads();
    }
    int off = part[t] - sum;   // exclusive
#pragma unroll 4
    for (int i = 0; i < CHUNK; i++) {
        next[base + i] = off;
        off += cnt[base + i];
    }
}

__global__ __launch_bounds__(THREADS) void scatter_kernel(
    const int* __restrict__ ei, int* __restrict__ next,
    int* __restrict__ ssrc, int* __restrict__ sdst, int E, int total)
{
    int e = blockIdx.x * blockDim.x + threadIdx.x;
    if (e < total) {
        int s, d;
        if (e < E) { s = ei[e]; d = ei[E + e]; }
        else       { s = e - E; d = s; }
        int pos = atomicAdd(&next[d], 1);
        ssrc[pos] = s;
        sdst[pos] = d;
    }
}

// W2[k][n] -> W2T[n][k], tf32-rounded
__global__ __launch_bounds__(HD) void prep_w2t_kernel(
    const float* __restrict__ W2, float* __restrict__ out)
{
    int n = blockIdx.x, k = threadIdx.x;
    float v = W2[k * HD + n];
    asm("cvt.rna.tf32.f32 %0, %0;" : "+f"(v));
    out[n * HD + k] = v;
}

// ---------------- node GEMM (fp32 FFMA) ----------------
__global__ __launch_bounds__(THREADS) void gemm_kernel(
    const float* __restrict__ In, const float* __restrict__ W,
    const float* __restrict__ bias, const float* __restrict__ addend,
    float* __restrict__ Out, int relu_out)
{
    __shared__ float sIn[16 * 128];
    __shared__ float sW[16 * 128];

    int tid = threadIdx.x;
    int rowBase = blockIdx.x * 128;
    int tx = tid & 15, ty = tid >> 4;

    float acc[8][8];
#pragma unroll
    for (int i = 0; i < 8; i++)
#pragma unroll
        for (int j = 0; j < 8; j++) acc[i][j] = 0.f;

    for (int kk = 0; kk < HD; kk += 16) {
#pragma unroll
        for (int l = 0; l < 2; l++) {
            int idx = tid + l * THREADS;
            int r = idx >> 2, c4 = idx & 3;
            float4 v = *(const float4*)(In + (size_t)(rowBase + r) * HD + kk + c4 * 4);
            sIn[(c4 * 4 + 0) * 128 + r] = v.x;
            sIn[(c4 * 4 + 1) * 128 + r] = v.y;
            sIn[(c4 * 4 + 2) * 128 + r] = v.z;
            sIn[(c4 * 4 + 3) * 128 + r] = v.w;
        }
#pragma unroll
        for (int l = 0; l < 2; l++) {
            int idx = tid + l * THREADS;
            int k = idx >> 5, c = idx & 31;
            *(float4*)(sW + k * 128 + c * 4) =
                *(const float4*)(W + (size_t)(kk + k) * HD + c * 4);
        }
        __syncthreads();
#pragma unroll
        for (int k = 0; k < 16; k++) {
            float a[8], b[8];
            *(float4*)(a)     = *(const float4*)(sIn + k * 128 + ty * 8);
            *(float4*)(a + 4) = *(const float4*)(sIn + k * 128 + ty * 8 + 4);
            *(float4*)(b)     = *(const float4*)(sW + k * 128 + tx * 8);
            *(float4*)(b + 4) = *(const float4*)(sW + k * 128 + tx * 8 + 4);
#pragma unroll
            for (int i = 0; i < 8; i++)
#pragma unroll
                for (int j = 0; j < 8; j++) acc[i][j] += a[i] * b[j];
        }
        __syncthreads();
    }

    float bv[8];
    if (bias) {
        *(float4*)(bv)     = *(const float4*)(bias + tx * 8);
        *(float4*)(bv + 4) = *(const float4*)(bias + tx * 8 + 4);
    } else {
#pragma unroll
        for (int j = 0; j < 8; j++) bv[j] = 0.f;
    }
#pragma unroll
    for (int i = 0; i < 8; i++) {
        size_t row = (size_t)rowBase + ty * 8 + i;
        float o[8];
#pragma unroll
        for (int j = 0; j < 8; j++) o[j] = acc[i][j] + bv[j];
        if (addend) {
            float4 a0 = *(const float4*)(addend + row * HD + tx * 8);
            float4 a1 = *(const float4*)(addend + row * HD + tx * 8 + 4);
            o[0] += a0.x; o[1] += a0.y; o[2] += a0.z; o[3] += a0.w;
            o[4] += a1.x; o[5] += a1.y; o[6] += a1.z; o[7] += a1.w;
        }
        if (relu_out) {
#pragma unroll
            for (int j = 0; j < 8; j++) o[j] = fmaxf(o[j], 0.f);
        }
        *(float4*)(Out + row * HD + tx * 8)     = make_float4(o[0], o[1], o[2], o[3]);
        *(float4*)(Out + row * HD + tx * 8 + 4) = make_float4(o[4], o[5], o[6], o[7]);
    }
}

// ---------------- edge kernel: tf32 mma + segmented max epilogue ----------------
__device__ __forceinline__ void mma_tf32(float* d, const uint32_t* a, const uint32_t* b) {
    asm volatile(
        "mma.sync.aligned.m16n8k8.row.col.f32.tf32.tf32.f32 "
        "{%0,%1,%2,%3}, {%4,%5,%6,%7}, {%8,%9}, {%0,%1,%2,%3};"
        : "+f"(d[0]), "+f"(d[1]), "+f"(d[2]), "+f"(d[3])
        : "r"(a[0]), "r"(a[1]), "r"(a[2]), "r"(a[3]), "r"(b[0]), "r"(b[1]));
}

__device__ __forceinline__ void atomic_fmax(float* p, float v) {
    if (v >= 0.f) atomicMax((int*)p, __float_as_int(v));
    else          atomicMin((unsigned int*)p, __float_as_uint(v));
}

__global__ __launch_bounds__(THREADS) void edge_mma_kernel(
    const int* __restrict__ ssrc, const int* __restrict__ sdst,
    const float* __restrict__ A, const float* __restrict__ B,
    const float* __restrict__ W2T, const float* __restrict__ b2,
    float* __restrict__ agg, int total)
{
    extern __shared__ char smem[];
    int* sDst = (int*)smem;
    float* sBias = (float*)(smem + 512);
    float* sT = (float*)(smem + SM_T);
    float* sW = (float*)(smem + SM_W);

    int tid = threadIdx.x;
    int lane = tid & 31, wid = tid >> 5;
    int eBase = blockIdx.x * 128;

    // Stream W2T into sW (padded rows) via cp.async, overlapping the gather
    {
        uint32_t sw_base;
        asm("{ .reg .u64 t; cvta.to.shared.u64 t, %1; cvt.u32.u64 %0, t; }"
            : "=r"(sw_base) : "l"(sW));
#pragma unroll
        for (int it = 0; it < 16; it++) {
            int linear = tid + it * THREADS;       // float4 index 0..4095
            int n = linear >> 5, c4 = linear & 31;
            uint32_t dst = sw_base + (uint32_t)(n * TS + c4 * 4) * 4;
            asm volatile("cp.async.cg.shared.global [%0], [%1], 16;"
                         :: "r"(dst), "l"(W2T + (size_t)linear * 4));
        }
        asm volatile("cp.async.commit_group;" ::: "memory");
    }

    if (tid < 128) sBias[tid] = b2[tid];

    // Gather (sorted edges): t = relu(A[src]-B[dst]) -> tf32 -> sT[row][k]
    {
        int r = tid >> 1, half = tid & 1;
        int e = eBase + r;
        bool valid = e < total;
        int s = 0, d = 0;
        if (valid) { s = ssrc[e]; d = sdst[e]; }
        if (half == 0) sDst[r] = valid ? d : -1;
        const float4* Ar = (const float4*)(A + (size_t)s * HD) + half * 16;
        const float4* Br = (const float4*)(B + (size_t)d * HD) + half * 16;
        float* Tr = sT + r * TS + half * 64;
#pragma unroll
        for (int q = 0; q < 16; q++) {
            float4 av = Ar[q], bw = Br[q];
            float4 t;
            t.x = valid ? fmaxf(av.x - bw.x, 0.f) : 0.f;
            t.y = valid ? fmaxf(av.y - bw.y, 0.f) : 0.f;
            t.z = valid ? fmaxf(av.z - bw.z, 0.f) : 0.f;
            t.w = valid ? fmaxf(av.w - bw.w, 0.f) : 0.f;
            asm("cvt.rna.tf32.f32 %0, %0;" : "+f"(t.x));
            asm("cvt.rna.tf32.f32 %0, %0;" : "+f"(t.y));
            asm("cvt.rna.tf32.f32 %0, %0;" : "+f"(t.z));
            asm("cvt.rna.tf32.f32 %0, %0;" : "+f"(t.w));
            *(float4*)(Tr + q * 4) = t;
        }
    }

    asm volatile("cp.async.wait_group 0;" ::: "memory");
    __syncthreads();

    // Warp tiles: warpM = wid&1 (rows 64), warpN = wid>>1 (cols 32)
    int rowBase = (wid & 1) * 64;
    int colBase = (wid >> 1) * 32;
    int g = lane >> 2, tg = lane & 3;

    float acc[4][4][4];
#pragma unroll
    for (int i = 0; i < 4; i++)
#pragma unroll
        for (int j = 0; j < 4; j++)
#pragma unroll
            for (int q = 0; q < 4; q++) acc[i][j][q] = 0.f;

    const uint32_t* sTu = (const uint32_t*)sT;
    const uint32_t* sWu = (const uint32_t*)sW;

#pragma unroll
    for (int ks = 0; ks < 16; ks++) {
        int kk = ks * 8;
        uint32_t b[4][2];
#pragma unroll
        for (int nf = 0; nf < 4; nf++) {
            int n = colBase + nf * 8 + g;
            b[nf][0] = sWu[n * TS + kk + tg];
            b[nf][1] = sWu[n * TS + kk + tg + 4];
        }
        uint32_t a[4][4];
#pragma unroll
        for (int mf = 0; mf < 4; mf++) {
            int r = rowBase + mf * 16 + g;
            a[mf][0] = sTu[r * TS + kk + tg];
            a[mf][1] = sTu[(r + 8) * TS + kk + tg];
            a[mf][2] = sTu[r * TS + kk + tg + 4];
            a[mf][3] = sTu[(r + 8) * TS + kk + tg + 4];
        }
#pragma unroll
        for (int mf = 0; mf < 4; mf++)
#pragma unroll
            for (int nf = 0; nf < 4; nf++)
                mma_tf32(acc[mf][nf], a[mf], b[nf]);
    }

    __syncthreads();   // all reads of sT done; reuse sT as output buffer

    // Write acc + bias -> sT[row][col]
#pragma unroll
    for (int mf = 0; mf < 4; mf++) {
        int r0 = rowBase + mf * 16 + g;
#pragma unroll
        for (int nf = 0; nf < 4; nf++) {
            int c0 = colBase + nf * 8 + 2 * tg;
            float b0 = sBias[c0], b1 = sBias[c0 + 1];
            float2 v0 = make_float2(acc[mf][nf][0] + b0, acc[mf][nf][1] + b1);
            float2 v1 = make_float2(acc[mf][nf][2] + b0, acc[mf][nf][3] + b1);
            *(float2*)(sT + r0 * TS + c0)       = v0;
            *(float2*)(sT + (r0 + 8) * TS + c0) = v1;
        }
    }
    __syncthreads();

    // Segmented column-max: rows sorted by dst within CTA; one atomic per
    // (segment, column). Two halves of 64 rows handled in parallel.
    {
        int c = tid & 127;
        int h = tid >> 7;
        int rstart = h * 64, rend = rstart + 64;
        int prev = sDst[rstart];
        float m = -FLT_MAX;
        for (int r = rstart; r < rend; r++) {
            int d = sDst[r];
            if (d != prev) {
                if (prev >= 0) atomic_fmax(agg + (size_t)prev * HD + c, m);
                m = -FLT_MAX;
                prev = d;
            }
            m = fmaxf(m, sT[r * TS + c]);
        }
        if (prev >= 0) atomic_fmax(agg + (size_t)prev * HD + c, m);
    }
}

// ---------------- launch ----------------
extern "C" void kernel_launch(void* const* d_in, const int* in_sizes, int n_in,
                              void* d_out, int out_size)
{
    (void)n_in; (void)out_size;
    const float* x   = (const float*)d_in[0];
    const float* pos = (const float*)d_in[1];
    const int* ei    = (const int*)d_in[2];
    const float* p[16];
    for (int i = 0; i < 16; i++) p[i] = (const float*)d_in[3 + i];

    int E = in_sizes[2] / 2;
    int total = E + NODES;

    float *A, *B, *AGG, *H0, *TMP, *W2T;
    int *CNT, *NEXT, *SSRC, *SDST;
    cudaGetSymbolAddress((void**)&A, g_A);
    cudaGetSymbolAddress((void**)&B, g_B);
    cudaGetSymbolAddress((void**)&AGG, g_agg);
    cudaGetSymbolAddress((void**)&H0, g_h0);
    cudaGetSymbolAddress((void**)&TMP, g_tmp);
    cudaGetSymbolAddress((void**)&W2T, g_w2t);
    cudaGetSymbolAddress((void**)&CNT, g_cnt);
    cudaGetSymbolAddress((void**)&NEXT, g_next);
    cudaGetSymbolAddress((void**)&SSRC, g_ssrc);
    cudaGetSymbolAddress((void**)&SDST, g_sdst);

    cudaFuncSetAttribute(edge_mma_kernel, cudaFuncAttributeMaxDynamicSharedMemorySize, EDGE_SMEM);

    int gemmBlocks = NODES / 128;              // 512
    int edgeBlocks = (total + 127) / 128;      // 8704
    int fillBlocks = (NODES * HD / 4 + THREADS - 1) / THREADS;
    int eBlocks = (total + THREADS - 1) / THREADS;

    // Build dst-sorted edge list once (layer-invariant)
    zero_i32<<<(NODES + THREADS - 1) / THREADS, THREADS>>>(CNT, NODES);
    hist_kernel<<<eBlocks, THREADS>>>(ei, CNT, E, total);
    scan_kernel<<<1, SCAN_T>>>(CNT, NEXT);
    scatter_kernel<<<eBlocks, THREADS>>>(ei, NEXT, SSRC, SDST, E, total);

    for (int layer = 0; layer < 2; layer++) {
        const float* lw1 = p[layer * 8 + 0];
        const float* lb1 = p[layer * 8 + 1];
        const float* lw2 = p[layer * 8 + 2];
        const float* lb2 = p[layer * 8 + 3];
        const float* gw1 = p[layer * 8 + 4];
        const float* gb1 = p[layer * 8 + 5];
        const float* gw2 = p[layer * 8 + 6];
        const float* gb2 = p[layer * 8 + 7];
        const float* inx = (layer == 0) ? x : H0;
        float* outp = (layer == 0) ? H0 : (float*)d_out;

        gemm_kernel<<<gemmBlocks, THREADS>>>(pos, lw1 + 128 * HD, nullptr, nullptr, B, 0);
        gemm_kernel<<<gemmBlocks, THREADS>>>(inx, lw1, lb1, B, A, 0);
        prep_w2t_kernel<<<HD, HD>>>(lw2, W2T);
        fill_kernel<<<fillBlocks, THREADS>>>((float4*)AGG, -FLT_MAX, NODES * HD / 4);
        edge_mma_kernel<<<edgeBlocks, THREADS, EDGE_SMEM>>>(SSRC, SDST, A, B, W2T, lb2, AGG, total);
        gemm_kernel<<<gemmBlocks, THREADS>>>(AGG, gw1, gb1, nullptr, TMP, 1);
        gemm_kernel<<<gemmBlocks, THREADS>>>(TMP, gw2, gb2, nullptr, outp, 0);
    }
}

// round 6
// speedup vs baseline: 1.8678x; 1.1517x over previous
#include <cuda_runtime.h>
#include <float.h>
#include <stdint.h>

#define NODES 65536
#define HD 128
#define THREADS 256
#define TS 132                       // smem row stride (floats) for sT/sW
#define MAXEDGES (1048576 + NODES)
#define GRID_EDGE 152

// persistent edge kernel smem map
// 0: sDst0 (512B) | 512: sDst1 (512B) | 1024: sBias (512B) | 2048: sT0 | sT1 | sW
#define TILE_BYTES (128 * TS * 4)    // 67584
#define SM_T0 2048
#define SM_T1 (2048 + TILE_BYTES)
#define SM_W  (2048 + 2 * TILE_BYTES)
#define EDGE_SMEM (2048 + 3 * TILE_BYTES)   // 204800 B

// ---------------- scratch ----------------
__device__ float g_A[(size_t)NODES * HD];
__device__ float g_B[(size_t)NODES * HD];
__device__ float g_agg[(size_t)NODES * HD];
__device__ float g_h0[(size_t)NODES * HD];
__device__ float g_tmp[(size_t)NODES * HD];
__device__ float g_w2t[HD * HD];     // W2^T, tf32-rounded, [n][k]
__device__ int g_cnt[NODES];
__device__ int g_next[NODES];
__device__ int g_ssrc[MAXEDGES];
__device__ int g_sdst[MAXEDGES];

__global__ __launch_bounds__(THREADS) void fill_kernel(float4* p, float v, int n4) {
    int i = blockIdx.x * blockDim.x + threadIdx.x;
    if (i < n4) p[i] = make_float4(v, v, v, v);
}

__global__ __launch_bounds__(THREADS) void zero_i32(int* p, int n) {
    int i = blockIdx.x * blockDim.x + threadIdx.x;
    if (i < n) p[i] = 0;
}

// ---------------- counting sort by dst (once per launch) ----------------
__global__ __launch_bounds__(THREADS) void hist_kernel(
    const int* __restrict__ ei, int* __restrict__ cnt, int E, int total)
{
    int e = blockIdx.x * blockDim.x + threadIdx.x;
    if (e < total) {
        int d = (e < E) ? ei[E + e] : (e - E);
        atomicAdd(&cnt[d], 1);
    }
}

#define SCAN_T 1024
#define CHUNK (NODES / SCAN_T)   // 64
__global__ __launch_bounds__(SCAN_T) void scan_kernel(
    const int* __restrict__ cnt, int* __restrict__ next)
{
    __shared__ int part[SCAN_T];
    int t = threadIdx.x;
    int base = t * CHUNK;
    int sum = 0;
#pragma unroll 4
    for (int i = 0; i < CHUNK; i++) sum += cnt[base + i];
    part[t] = sum;
    __syncthreads();
    for (int off = 1; off < SCAN_T; off <<= 1) {
        int v = (t >= off) ? part[t - off] : 0;
        __syncthreads();
        part[t] += v;
        __syncthreads();
    }
    int off = part[t] - sum;   // exclusive
#pragma unroll 4
    for (int i = 0; i < CHUNK; i++) {
        next[base + i] = off;
        off += cnt[base + i];
    }
}

__global__ __launch_bounds__(THREADS) void scatter_kernel(
    const int* __restrict__ ei, int* __restrict__ next,
    int* __restrict__ ssrc, int* __restrict__ sdst, int E, int total)
{
    int e = blockIdx.x * blockDim.x + threadIdx.x;
    if (e < total) {
        int s, d;
        if (e < E) { s = ei[e]; d = ei[E + e]; }
        else       { s = e - E; d = s; }
        int pos = atomicAdd(&next[d], 1);
        ssrc[pos] = s;
        sdst[pos] = d;
    }
}

// W2[k][n] -> W2T[n][k], tf32-rounded
__global__ __launch_bounds__(HD) void prep_w2t_kernel(
    const float* __restrict__ W2, float* __restrict__ out)
{
    int n = blockIdx.x, k = threadIdx.x;
    float v = W2[k * HD + n];
    asm("cvt.rna.tf32.f32 %0, %0;" : "+f"(v));
    out[n * HD + k] = v;
}

// ---------------- node GEMM (fp32 FFMA) ----------------
__global__ __launch_bounds__(THREADS) void gemm_kernel(
    const float* __restrict__ In, const float* __restrict__ W,
    const float* __restrict__ bias, const float* __restrict__ addend,
    float* __restrict__ Out, int relu_out)
{
    __shared__ float sIn[16 * 128];
    __shared__ float sW[16 * 128];

    int tid = threadIdx.x;
    int rowBase = blockIdx.x * 128;
    int tx = tid & 15, ty = tid >> 4;

    float acc[8][8];
#pragma unroll
    for (int i = 0; i < 8; i++)
#pragma unroll
        for (int j = 0; j < 8; j++) acc[i][j] = 0.f;

    for (int kk = 0; kk < HD; kk += 16) {
#pragma unroll
        for (int l = 0; l < 2; l++) {
            int idx = tid + l * THREADS;
            int r = idx >> 2, c4 = idx & 3;
            float4 v = *(const float4*)(In + (size_t)(rowBase + r) * HD + kk + c4 * 4);
            sIn[(c4 * 4 + 0) * 128 + r] = v.x;
            sIn[(c4 * 4 + 1) * 128 + r] = v.y;
            sIn[(c4 * 4 + 2) * 128 + r] = v.z;
            sIn[(c4 * 4 + 3) * 128 + r] = v.w;
        }
#pragma unroll
        for (int l = 0; l < 2; l++) {
            int idx = tid + l * THREADS;
            int k = idx >> 5, c = idx & 31;
            *(float4*)(sW + k * 128 + c * 4) =
                *(const float4*)(W + (size_t)(kk + k) * HD + c * 4);
        }
        __syncthreads();
#pragma unroll
        for (int k = 0; k < 16; k++) {
            float a[8], b[8];
            *(float4*)(a)     = *(const float4*)(sIn + k * 128 + ty * 8);
            *(float4*)(a + 4) = *(const float4*)(sIn + k * 128 + ty * 8 + 4);
            *(float4*)(b)     = *(const float4*)(sW + k * 128 + tx * 8);
            *(float4*)(b + 4) = *(const float4*)(sW + k * 128 + tx * 8 + 4);
#pragma unroll
            for (int i = 0; i < 8; i++)
#pragma unroll
                for (int j = 0; j < 8; j++) acc[i][j] += a[i] * b[j];
        }
        __syncthreads();
    }

    float bv[8];
    if (bias) {
        *(float4*)(bv)     = *(const float4*)(bias + tx * 8);
        *(float4*)(bv + 4) = *(const float4*)(bias + tx * 8 + 4);
    } else {
#pragma unroll
        for (int j = 0; j < 8; j++) bv[j] = 0.f;
    }
#pragma unroll
    for (int i = 0; i < 8; i++) {
        size_t row = (size_t)rowBase + ty * 8 + i;
        float o[8];
#pragma unroll
        for (int j = 0; j < 8; j++) o[j] = acc[i][j] + bv[j];
        if (addend) {
            float4 a0 = *(const float4*)(addend + row * HD + tx * 8);
            float4 a1 = *(const float4*)(addend + row * HD + tx * 8 + 4);
            o[0] += a0.x; o[1] += a0.y; o[2] += a0.z; o[3] += a0.w;
            o[4] += a1.x; o[5] += a1.y; o[6] += a1.z; o[7] += a1.w;
        }
        if (relu_out) {
#pragma unroll
            for (int j = 0; j < 8; j++) o[j] = fmaxf(o[j], 0.f);
        }
        *(float4*)(Out + row * HD + tx * 8)     = make_float4(o[0], o[1], o[2], o[3]);
        *(float4*)(Out + row * HD + tx * 8 + 4) = make_float4(o[4], o[5], o[6], o[7]);
    }
}

// ---------------- persistent edge kernel ----------------
__device__ __forceinline__ void mma_tf32(float* d, const uint32_t* a, const uint32_t* b) {
    asm volatile(
        "mma.sync.aligned.m16n8k8.row.col.f32.tf32.tf32.f32 "
        "{%0,%1,%2,%3}, {%4,%5,%6,%7}, {%8,%9}, {%0,%1,%2,%3};"
        : "+f"(d[0]), "+f"(d[1]), "+f"(d[2]), "+f"(d[3])
        : "r"(a[0]), "r"(a[1]), "r"(a[2]), "r"(a[3]), "r"(b[0]), "r"(b[1]));
}

__device__ __forceinline__ void atomic_fmax(float* p, float v) {
    if (v >= 0.f) atomicMax((int*)p, __float_as_int(v));
    else          atomicMin((unsigned int*)p, __float_as_uint(v));
}

struct GReg {
    float4 a[8], b[8];
    int d, r;
    bool valid;
};

__device__ __forceinline__ void gather_issue(
    int eBase, int pass, GReg& G,
    const int* __restrict__ ssrc, const int* __restrict__ sdst,
    const float* __restrict__ A, const float* __restrict__ B,
    int total, int tid)
{
    int r = pass * 64 + (tid >> 2);
    int q = tid & 3;
    int e = eBase + r;
    G.valid = (e < total);
    int s = 0, d = 0;
    if (G.valid) { s = ssrc[e]; d = sdst[e]; }
    G.d = d; G.r = r;
    const float4* Ar = (const float4*)(A + (size_t)s * HD) + q;
    const float4* Br = (const float4*)(B + (size_t)d * HD) + q;
#pragma unroll
    for (int i = 0; i < 8; i++) {
        G.a[i] = Ar[i * 4];   // float4 index q + 4i (coalesced groups of 4 lanes)
        G.b[i] = Br[i * 4];
    }
}

__device__ __forceinline__ void gather_commit(
    const GReg& G, float* __restrict__ sTn, int* __restrict__ sDn, int tid)
{
    int q = tid & 3;
    if (q == 0) sDn[G.r] = G.valid ? G.d : -1;
    float* Tr = sTn + G.r * TS + q * 4;
#pragma unroll
    for (int i = 0; i < 8; i++) {
        float4 t;
        t.x = G.valid ? fmaxf(G.a[i].x - G.b[i].x, 0.f) : 0.f;
        t.y = G.valid ? fmaxf(G.a[i].y - G.b[i].y, 0.f) : 0.f;
        t.z = G.valid ? fmaxf(G.a[i].z - G.b[i].z, 0.f) : 0.f;
        t.w = G.valid ? fmaxf(G.a[i].w - G.b[i].w, 0.f) : 0.f;
        asm("cvt.rna.tf32.f32 %0, %0;" : "+f"(t.x));
        asm("cvt.rna.tf32.f32 %0, %0;" : "+f"(t.y));
        asm("cvt.rna.tf32.f32 %0, %0;" : "+f"(t.z));
        asm("cvt.rna.tf32.f32 %0, %0;" : "+f"(t.w));
        *(float4*)(Tr + i * 16) = t;   // float col = q*4 + 16*i
    }
}

__device__ __forceinline__ void mma_half(
    const float* __restrict__ sT, const float* __restrict__ sW,
    int kk0, float acc[4][4][4], int rowBase, int colBase, int g, int tg)
{
    const uint32_t* sTu = (const uint32_t*)sT;
    const uint32_t* sWu = (const uint32_t*)sW;
#pragma unroll
    for (int ks = 0; ks < 8; ks++) {
        int kk = kk0 + ks * 8;
        uint32_t b[4][2];
#pragma unroll
        for (int nf = 0; nf < 4; nf++) {
            int n = colBase + nf * 8 + g;
            b[nf][0] = sWu[n * TS + kk + tg];
            b[nf][1] = sWu[n * TS + kk + tg + 4];
        }
        uint32_t a[4][4];
#pragma unroll
        for (int mf = 0; mf < 4; mf++) {
            int r = rowBase + mf * 16 + g;
            a[mf][0] = sTu[r * TS + kk + tg];
            a[mf][1] = sTu[(r + 8) * TS + kk + tg];
            a[mf][2] = sTu[r * TS + kk + tg + 4];
            a[mf][3] = sTu[(r + 8) * TS + kk + tg + 4];
        }
#pragma unroll
        for (int mf = 0; mf < 4; mf++)
#pragma unroll
            for (int nf = 0; nf < 4; nf++)
                mma_tf32(acc[mf][nf], a[mf], b[nf]);
    }
}

__global__ __launch_bounds__(THREADS, 1) void edge_mma_kernel(
    const int* __restrict__ ssrc, const int* __restrict__ sdst,
    const float* __restrict__ A, const float* __restrict__ B,
    const float* __restrict__ W2T, const float* __restrict__ b2,
    float* __restrict__ agg, int total)
{
    extern __shared__ char smem[];
    int* sDst0 = (int*)smem;
    int* sDst1 = (int*)(smem + 512);
    float* sBias = (float*)(smem + 1024);
    float* sT0 = (float*)(smem + SM_T0);
    float* sT1 = (float*)(smem + SM_T1);
    float* sW  = (float*)(smem + SM_W);

    int tid = threadIdx.x;
    int lane = tid & 31, wid = tid >> 5;
    int ntiles = (total + 127) >> 7;

    // One-time: stream W2T into sW (padded rows) via cp.async
    {
        uint32_t sw_base;
        asm("{ .reg .u64 t; cvta.to.shared.u64 t, %1; cvt.u32.u64 %0, t; }"
            : "=r"(sw_base) : "l"(sW));
#pragma unroll
        for (int it = 0; it < 16; it++) {
            int linear = tid + it * THREADS;       // float4 index 0..4095
            int n = linear >> 5, c4 = linear & 31;
            uint32_t dst = sw_base + (uint32_t)(n * TS + c4 * 4) * 4;
            asm volatile("cp.async.cg.shared.global [%0], [%1], 16;"
                         :: "r"(dst), "l"(W2T + (size_t)linear * 4));
        }
        asm volatile("cp.async.commit_group;" ::: "memory");
    }
    if (tid < 128) sBias[tid] = b2[tid];

    // Prologue: gather first tile into buffer 0
    if (blockIdx.x < ntiles) {
        GReg G;
        gather_issue(blockIdx.x * 128, 0, G, ssrc, sdst, A, B, total, tid);
        gather_commit(G, sT0, sDst0, tid);
        gather_issue(blockIdx.x * 128, 1, G, ssrc, sdst, A, B, total, tid);
        gather_commit(G, sT0, sDst0, tid);
    }
    asm volatile("cp.async.wait_group 0;" ::: "memory");
    __syncthreads();

    int rowBase = (wid & 1) * 64;
    int colBase = (wid >> 1) * 32;
    int g = lane >> 2, tg = lane & 3;

    int buf = 0;
    for (int ti = blockIdx.x; ti < ntiles; ti += GRID_EDGE) {
        float* sTc = buf ? sT1 : sT0;
        float* sTn = buf ? sT0 : sT1;
        int* sDc = buf ? sDst1 : sDst0;
        int* sDn = buf ? sDst0 : sDst1;
        int tn = ti + GRID_EDGE;
        bool hn = tn < ntiles;

        float acc[4][4][4];
#pragma unroll
        for (int i = 0; i < 4; i++)
#pragma unroll
            for (int j = 0; j < 4; j++)
#pragma unroll
                for (int q = 0; q < 4; q++) acc[i][j][q] = 0.f;

        GReg G;
        if (hn) gather_issue(tn * 128, 0, G, ssrc, sdst, A, B, total, tid);
        mma_half(sTc, sW, 0, acc, rowBase, colBase, g, tg);
        if (hn) {
            gather_commit(G, sTn, sDn, tid);
            gather_issue(tn * 128, 1, G, ssrc, sdst, A, B, total, tid);
        }
        mma_half(sTc, sW, 64, acc, rowBase, colBase, g, tg);
        if (hn) gather_commit(G, sTn, sDn, tid);

        __syncthreads();   // all MMA reads of sTc complete

        // stage acc + bias into sTc
#pragma unroll
        for (int mf = 0; mf < 4; mf++) {
            int r0 = rowBase + mf * 16 + g;
#pragma unroll
            for (int nf = 0; nf < 4; nf++) {
                int c0 = colBase + nf * 8 + 2 * tg;
                float b0 = sBias[c0], b1 = sBias[c0 + 1];
                *(float2*)(sTc + r0 * TS + c0) =
                    make_float2(acc[mf][nf][0] + b0, acc[mf][nf][1] + b1);
                *(float2*)(sTc + (r0 + 8) * TS + c0) =
                    make_float2(acc[mf][nf][2] + b0, acc[mf][nf][3] + b1);
            }
        }
        __syncthreads();

        // segmented column-max (rows sorted by dst); one atomic per (segment,col)
        {
            int c = tid & 127;
            int h = tid >> 7;
            int rstart = h * 64, rend = rstart + 64;
            int prev = sDc[rstart];
            float m = -FLT_MAX;
            for (int r = rstart; r < rend; r++) {
                int d = sDc[r];
                if (d != prev) {
                    if (prev >= 0) atomic_fmax(agg + (size_t)prev * HD + c, m);
                    m = -FLT_MAX;
                    prev = d;
                }
                m = fmaxf(m, sTc[r * TS + c]);
            }
            if (prev >= 0) atomic_fmax(agg + (size_t)prev * HD + c, m);
        }
        __syncthreads();
        buf ^= 1;
    }
}

// ---------------- launch ----------------
extern "C" void kernel_launch(void* const* d_in, const int* in_sizes, int n_in,
                              void* d_out, int out_size)
{
    (void)n_in; (void)out_size;
    const float* x   = (const float*)d_in[0];
    const float* pos = (const float*)d_in[1];
    const int* ei    = (const int*)d_in[2];
    const float* p[16];
    for (int i = 0; i < 16; i++) p[i] = (const float*)d_in[3 + i];

    int E = in_sizes[2] / 2;
    int total = E + NODES;

    float *A, *B, *AGG, *H0, *TMP, *W2T;
    int *CNT, *NEXT, *SSRC, *SDST;
    cudaGetSymbolAddress((void**)&A, g_A);
    cudaGetSymbolAddress((void**)&B, g_B);
    cudaGetSymbolAddress((void**)&AGG, g_agg);
    cudaGetSymbolAddress((void**)&H0, g_h0);
    cudaGetSymbolAddress((void**)&TMP, g_tmp);
    cudaGetSymbolAddress((void**)&W2T, g_w2t);
    cudaGetSymbolAddress((void**)&CNT, g_cnt);
    cudaGetSymbolAddress((void**)&NEXT, g_next);
    cudaGetSymbolAddress((void**)&SSRC, g_ssrc);
    cudaGetSymbolAddress((void**)&SDST, g_sdst);

    cudaFuncSetAttribute(edge_mma_kernel, cudaFuncAttributeMaxDynamicSharedMemorySize, EDGE_SMEM);

    int gemmBlocks = NODES / 128;              // 512
    int fillBlocks = (NODES * HD / 4 + THREADS - 1) / THREADS;
    int eBlocks = (total + THREADS - 1) / THREADS;

    // Build dst-sorted edge list once (layer-invariant)
    zero_i32<<<(NODES + THREADS - 1) / THREADS, THREADS>>>(CNT, NODES);
    hist_kernel<<<eBlocks, THREADS>>>(ei, CNT, E, total);
    scan_kernel<<<1, SCAN_T>>>(CNT, NEXT);
    scatter_kernel<<<eBlocks, THREADS>>>(ei, NEXT, SSRC, SDST, E, total);

    for (int layer = 0; layer < 2; layer++) {
        const float* lw1 = p[layer * 8 + 0];
        const float* lb1 = p[layer * 8 + 1];
        const float* lw2 = p[layer * 8 + 2];
        const float* lb2 = p[layer * 8 + 3];
        const float* gw1 = p[layer * 8 + 4];
        const float* gb1 = p[layer * 8 + 5];
        const float* gw2 = p[layer * 8 + 6];
        const float* gb2 = p[layer * 8 + 7];
        const float* inx = (layer == 0) ? x : H0;
        float* outp = (layer == 0) ? H0 : (float*)d_out;

        gemm_kernel<<<gemmBlocks, THREADS>>>(pos, lw1 + 128 * HD, nullptr, nullptr, B, 0);
        gemm_kernel<<<gemmBlocks, THREADS>>>(inx, lw1, lb1, B, A, 0);
        prep_w2t_kernel<<<HD, HD>>>(lw2, W2T);
        fill_kernel<<<fillBlocks, THREADS>>>((float4*)AGG, -FLT_MAX, NODES * HD / 4);
        edge_mma_kernel<<<GRID_EDGE, THREADS, EDGE_SMEM>>>(SSRC, SDST, A, B, W2T, lb2, AGG, total);
        gemm_kernel<<<gemmBlocks, THREADS>>>(AGG, gw1, gb1, nullptr, TMP, 1);
        gemm_kernel<<<gemmBlocks, THREADS>>>(TMP, gw2, gb2, nullptr, outp, 0);
    }
}